// round 7
// baseline (speedup 1.0000x reference)
#include <cuda_runtime.h>
#include <cuda_bf16.h>
#include <math.h>
#include <stdint.h>

#define NB 16
#define NS 16384
#define NC 64
#define NM 16
#define NPSP 500
#define NPFR 200
#define NED 8
#define NCH 64          // DFT chunks over s (256 s each)

// -------- scratch (static device globals; no runtime allocation) -----------
__device__ float g_h[NB * NS * NC];                 // [b][s][c]  64 MB
__device__ float g_tw[NS * 32];                     // per s: cos[16], sin[16]
__device__ int   g_idx[NB * NS];                    // spatial engram idx
__device__ float g_xpart[NB * NCH * NC * 32];       // DFT partials (8 MB)
__device__ float g_epart[NB * 64 * NED];            // embedding partial sums
__device__ float g_cR[NB * NC * NM];                // combined mode coef (pre-scaled)
__device__ float g_cI[NB * NC * NM];
__device__ float g_w0[NB];                          // gate weight for sp branch

// ---------------------------------------------------------------------------
// fp32 twiddles with exact integer phase reduction
__global__ void k_twiddle() {
    int s = blockIdx.x * 256 + threadIdx.x;
    if (s >= NS) return;
#pragma unroll
    for (int k = 0; k < 16; k++) {
        int r = (k * s) & (NS - 1);
        float a = (float)r * (2.0f * 3.14159265358979323846f / (float)NS);
        float sv, cv; sincosf(a, &sv, &cv);
        g_tw[s * 32 + k]      = cv;
        g_tw[s * 32 + 16 + k] = sv;
    }
}

// lifting: h[b,s,c] = sum_ci x[b,ci,s] * W[ci,c] + bias[c]
__global__ void k_lift(const float* __restrict__ x,
                       const float* __restrict__ W,
                       const float* __restrict__ bias) {
    __shared__ float lw[3 * NC], lb[NC];
    int b = blockIdx.y, t = threadIdx.x;
    if (t < 192) lw[t] = W[t];
    if (t < NC)  lb[t] = bias[t];
    __syncthreads();
    int c = t & 63, sg = t >> 6;
    const float* xb = x + b * 3 * NS;
    for (int i = 0; i < 16; i++) {
        int s = blockIdx.x * 64 + i * 4 + sg;
        float x0 = xb[s], x1 = xb[NS + s], x2 = xb[2 * NS + s];
        g_h[(b * NS + s) * NC + c] = lb[c] + x0 * lw[c] + x1 * lw[64 + c] + x2 * lw[128 + c];
    }
}

// fused: channel sums (with 4-halo in smem) -> window hash -> idx + emb partials
__global__ void k_scidx(const float* __restrict__ sp_emb, int layer) {
    __shared__ float ssc[260];
    __shared__ float wred[8 * NED];
    int b = blockIdx.y, t = threadIdx.x;
    int base = blockIdx.x * 256;
    for (int j = t; j < 260; j += 256) {
        int s = base + j - 2;
        s = s < 0 ? 0 : (s > NS - 1 ? NS - 1 : s);
        const float4* hp = (const float4*)(g_h + (b * NS + s) * NC);
        float acc = 0.0f;
#pragma unroll
        for (int q = 0; q < 16; q++) {
            float4 v = hp[q];
            acc += v.x; acc += v.y; acc += v.z; acc += v.w;
        }
        ssc[j] = acc;
    }
    __syncthreads();
    int s = base + t;
    float w = ((ssc[t] + ssc[t + 1]) + ssc[t + 2]) + ssc[t + 3];
    int iv = (int)(w * 31.0f);
    iv = ((iv % NPSP) + NPSP) % NPSP;
    g_idx[b * NS + s] = iv;
    const float* em = sp_emb + (layer * NPSP + iv) * NED;
    float ev[NED];
#pragma unroll
    for (int e = 0; e < NED; e++) ev[e] = em[e];
#pragma unroll
    for (int off = 16; off > 0; off >>= 1) {
#pragma unroll
        for (int e = 0; e < NED; e++)
            ev[e] += __shfl_xor_sync(0xffffffffu, ev[e], off);
    }
    int wid = t >> 5, lid = t & 31;
    if (lid == 0) {
#pragma unroll
        for (int e = 0; e < NED; e++) wred[wid * NED + e] = ev[e];
    }
    __syncthreads();
    if (t < NED) {
        float acc = 0.f;
#pragma unroll
        for (int ww = 0; ww < 8; ww++) acc += wred[ww * NED + t];
        g_epart[(b * 64 + blockIdx.x) * NED + t] = acc;
    }
}

// 16-mode DFT partials. Thread map: c = t>>2 (0..63), g = t&3 (s-subgroup).
// No smem: cross-group reduce via in-warp shfl_down (order-preserving).
__global__ void k_dft() {
    int b = blockIdx.y, chunk = blockIdx.x, t = threadIdx.x;
    int c = t >> 2, g = t & 3;
    float aC[16], aS[16];
#pragma unroll
    for (int k = 0; k < 16; k++) { aC[k] = 0.f; aS[k] = 0.f; }
    const float* hb = g_h + b * NS * NC + c;
    for (int i = 0; i < 64; i += 2) {
        int s0 = chunk * 256 + i * 4 + g;
        int s1 = s0 + 4;
        float xv0 = hb[s0 * NC];
        float xv1 = hb[s1 * NC];
        const float4* tw0 = (const float4*)(g_tw + s0 * 32);
        const float4* tw1 = (const float4*)(g_tw + s1 * 32);
#pragma unroll
        for (int q = 0; q < 4; q++) {
            float4 tc = tw0[q];
            aC[4*q+0] += xv0 * tc.x; aC[4*q+1] += xv0 * tc.y;
            aC[4*q+2] += xv0 * tc.z; aC[4*q+3] += xv0 * tc.w;
            float4 ts = tw0[4 + q];
            aS[4*q+0] += xv0 * ts.x; aS[4*q+1] += xv0 * ts.y;
            aS[4*q+2] += xv0 * ts.z; aS[4*q+3] += xv0 * ts.w;
        }
#pragma unroll
        for (int q = 0; q < 4; q++) {
            float4 tc = tw1[q];
            aC[4*q+0] += xv1 * tc.x; aC[4*q+1] += xv1 * tc.y;
            aC[4*q+2] += xv1 * tc.z; aC[4*q+3] += xv1 * tc.w;
            float4 ts = tw1[4 + q];
            aS[4*q+0] += xv1 * ts.x; aS[4*q+1] += xv1 * ts.y;
            aS[4*q+2] += xv1 * ts.z; aS[4*q+3] += xv1 * ts.w;
        }
    }
    // reduce g=0..3 within each 4-lane group, left-associated (matches old order)
    const unsigned full = 0xffffffffu;
#pragma unroll
    for (int k = 0; k < 16; k++) {
        float c1 = __shfl_down_sync(full, aC[k], 1);
        float c2 = __shfl_down_sync(full, aC[k], 2);
        float c3 = __shfl_down_sync(full, aC[k], 3);
        aC[k] = ((aC[k] + c1) + c2) + c3;
        float s1_ = __shfl_down_sync(full, aS[k], 1);
        float s2_ = __shfl_down_sync(full, aS[k], 2);
        float s3_ = __shfl_down_sync(full, aS[k], 3);
        aS[k] = ((aS[k] + s1_) + s2_) + s3_;
    }
    if (g == 0) {
        float4* dst = (float4*)(g_xpart + ((b * NCH + chunk) * NC + c) * 32);
#pragma unroll
        for (int q = 0; q < 4; q++)
            dst[q] = make_float4(aC[4*q], aC[4*q+1], aC[4*q+2], aC[4*q+3]);
#pragma unroll
        for (int q = 0; q < 4; q++)
            dst[4 + q] = make_float4(aS[4*q], aS[4*q+1], aS[4*q+2], aS[4*q+3]);
    }
}

// per-b small math: X reduce, mags+fr hash, mh einsum, fr proj, gate MLP, coef combine
__global__ void k_small(const float* __restrict__ sp_W, const float* __restrict__ sp_b,
                        const float* __restrict__ fr_emb, const float* __restrict__ fr_W,
                        const float* __restrict__ fr_b,
                        const float* __restrict__ gW1, const float* __restrict__ gb1,
                        const float* __restrict__ gW2, const float* __restrict__ gb2,
                        const float* __restrict__ Wr, const float* __restrict__ Wi,
                        int layer) {
    __shared__ float sXR[1024], sXI[1024], sOR[1024], sOI[1024], sPR[1024];
    __shared__ float sMag[16], sEmb[8], sEm[8], sG[192], sH1[64], sW[3];
    __shared__ int sFidx;
    int b = blockIdx.x, t = threadIdx.x;
    const float invS = 1.0f / (float)NS;

    for (int it = 0; it < 4; it++) {
        int p = t + it * 256;            // p = c*16 + k
        int c = p >> 4, k = p & 15;
        float sc_ = 0.f, ss = 0.f;
        const float* src0 = g_xpart + (b * NCH * NC + c) * 32 + k;
#pragma unroll 8
        for (int ch = 0; ch < NCH; ch++) {
            const float* src = src0 + ch * NC * 32;
            sc_ += src[0]; ss += src[16];
        }
        sXR[p] = sc_; sXI[p] = -ss;      // rfft: Im = -sum x*sin
    }
    __syncthreads();

    if (t < 16) {
        float acc = 0.f;
        for (int c = 0; c < NC; c++) {
            float xr = sXR[c * 16 + t], xi = sXI[c * 16 + t];
            acc += sqrtf(xr * xr + xi * xi);
        }
        sMag[t] = acc * (1.0f / 64.0f);
    }
    __syncthreads();
    if (t == 0) {
        int s = 0;
        for (int m = 0; m < 16; m++) s += (int)(sMag[m] * 1000.0f);
        sFidx = ((s % NPFR) + NPFR) % NPFR;
    }
    __syncthreads();
    if (t < 8) sEmb[t] = fr_emb[(layer * NPFR + sFidx) * NED + t];

    for (int it = 0; it < 4; it++) {
        int p = t + it * 256;
        int oc = p >> 4, m = p & 15;
        int hh = oc >> 4, o = oc & 15;
        float aR = 0.f, aI = 0.f;
#pragma unroll 4
        for (int i = 0; i < 16; i++) {
            float xr = sXR[(hh * 16 + i) * 16 + m];
            float xi = sXI[(hh * 16 + i) * 16 + m];
            int wi_ = (((layer * 4 + hh) * 16 + i) * 16 + o) * 16 + m;
            float wr = Wr[wi_], wim = Wi[wi_];
            aR += xr * wr - xi * wim;
            aI += xr * wim + xi * wr;
        }
        sOR[p] = aR; sOI[p] = aI;
    }
    __syncthreads();

    for (int it = 0; it < 4; it++) {
        int p = t + it * 256;
        int c = p >> 4, m = p & 15;
        float acc = fr_b[layer * 1024 + c * 16 + m];
#pragma unroll
        for (int e = 0; e < NED; e++)
            acc += sEmb[e] * fr_W[(layer * NED + e) * 1024 + c * 16 + m];
        sPR[p] = acc;
    }

    if (t < 8) {
        float acc = 0.f;
#pragma unroll 8
        for (int blk = 0; blk < 64; blk++) acc += g_epart[(b * 64 + blk) * NED + t];
        sEm[t] = acc * invS;
    }
    __syncthreads();

    if (t < 64) {
        float sm = sp_b[layer * NC + t];
#pragma unroll
        for (int e = 0; e < NED; e++) sm += sEm[e] * sp_W[(layer * NED + e) * NC + t];
        sG[t]       = sm;
        sG[64 + t]  = sOR[t * 16] * invS;
        sG[128 + t] = sPR[t * 16] * invS;
    }
    __syncthreads();
    if (t < 64) {
        float acc = gb1[layer * 64 + t];
#pragma unroll 8
        for (int i = 0; i < 192; i++) acc += sG[i] * gW1[(layer * 192 + i) * 64 + t];
        sH1[t] = fmaxf(acc, 0.0f);
    }
    __syncthreads();
    if (t < 3) {
        float acc = gb2[layer * 3 + t];
        for (int i = 0; i < 64; i++) acc += sH1[i] * gW2[(layer * 64 + i) * 3 + t];
        sW[t] = acc;
    }
    __syncthreads();
    if (t == 0) {
        float mx = fmaxf(sW[0], fmaxf(sW[1], sW[2]));
        float e0 = expf(sW[0] - mx), e1 = expf(sW[1] - mx), e2 = expf(sW[2] - mx);
        float inv = 1.0f / (e0 + e1 + e2);
        sW[0] = e0 * inv; sW[1] = e1 * inv; sW[2] = e2 * inv;
        g_w0[b] = sW[0];
    }
    __syncthreads();

    float w1 = sW[1], w2 = sW[2];
    for (int it = 0; it < 4; it++) {
        int p = t + it * 256;
        int k = p & 15;
        float scale = (k == 0) ? invS : 2.0f * invS;
        g_cR[b * 1024 + p] = (w1 * sOR[p] + w2 * sPR[p]) * scale;
        g_cI[b * 1024 + p] = (w1 * sOI[p]) * scale;
    }
}

// fused synthesis: h = gelu( w0*sp + sum_k (cR cos - cI sin) ), in place
__global__ void k_synth(const float* __restrict__ sp_emb,
                        const float* __restrict__ sp_W,
                        const float* __restrict__ sp_b, int layer) {
    __shared__ float sw[NED * NC], sb[NC];
    int b = blockIdx.y, t = threadIdx.x;
    for (int p = t; p < NED * NC; p += 256) sw[p] = sp_W[layer * NED * NC + p];
    if (t < NC) sb[t] = sp_b[layer * NC + t];
    __syncthreads();
    int c = t & 63, sg = t >> 6;
    float cR[16], cI[16];
    const float* crp = g_cR + (b * NC + c) * NM;
    const float* cip = g_cI + (b * NC + c) * NM;
#pragma unroll
    for (int k = 0; k < 16; k++) { cR[k] = crp[k]; cI[k] = cip[k]; }
    float w0 = g_w0[b];
    for (int i = 0; i < 32; i += 2) {
        int s0 = blockIdx.x * 128 + i * 4 + sg;
        int s1 = s0 + 4;
        int iv0 = g_idx[b * NS + s0];
        int iv1 = g_idx[b * NS + s1];
        const float* em0 = sp_emb + (layer * NPSP + iv0) * NED;
        const float* em1 = sp_emb + (layer * NPSP + iv1) * NED;
        float spv0 = sb[c], spv1 = sb[c];
#pragma unroll
        for (int e = 0; e < NED; e++) {
            spv0 += em0[e] * sw[e * NC + c];
            spv1 += em1[e] * sw[e * NC + c];
        }
        const float4* tw0 = (const float4*)(g_tw + s0 * 32);
        const float4* tw1 = (const float4*)(g_tw + s1 * 32);
        float spec0 = 0.f, spec1 = 0.f;
#pragma unroll
        for (int q = 0; q < 4; q++) {
            float4 tc0 = tw0[q];
            spec0 += cR[4*q+0]*tc0.x + cR[4*q+1]*tc0.y + cR[4*q+2]*tc0.z + cR[4*q+3]*tc0.w;
            float4 ts0 = tw0[4 + q];
            spec0 -= cI[4*q+0]*ts0.x + cI[4*q+1]*ts0.y + cI[4*q+2]*ts0.z + cI[4*q+3]*ts0.w;
            float4 tc1 = tw1[q];
            spec1 += cR[4*q+0]*tc1.x + cR[4*q+1]*tc1.y + cR[4*q+2]*tc1.z + cR[4*q+3]*tc1.w;
            float4 ts1 = tw1[4 + q];
            spec1 -= cI[4*q+0]*ts1.x + cI[4*q+1]*ts1.y + cI[4*q+2]*ts1.z + cI[4*q+3]*ts1.w;
        }
        float v0 = w0 * spv0 + spec0;
        float v1 = w0 * spv1 + spec1;
        float gl0 = 0.5f * v0 * (1.0f + erff(v0 * 0.70710678118654752f));
        float gl1 = 0.5f * v1 * (1.0f + erff(v1 * 0.70710678118654752f));
        g_h[(b * NS + s0) * NC + c] = gl0;
        g_h[(b * NS + s1) * NC + c] = gl1;
    }
}

// projection: out[b,0,s] = sum_c h[b,s,c] * Wp[c] + bp
__global__ void k_proj(const float* __restrict__ Wp, const float* __restrict__ bp,
                       float* __restrict__ out) {
    __shared__ float pw[NC];
    int b = blockIdx.y, t = threadIdx.x;
    if (t < NC) pw[t] = Wp[t];
    __syncthreads();
    int s = blockIdx.x * 256 + t;
    const float* hp = g_h + (b * NS + s) * NC;
    float acc = 0.f;
#pragma unroll 16
    for (int c = 0; c < NC; c++) acc += hp[c] * pw[c];
    out[b * NS + s] = acc + bp[0];
}

extern "C" void kernel_launch(void* const* d_in, const int* in_sizes, int n_in,
                              void* d_out, int out_size) {
    const float* x      = (const float*)d_in[0];
    const float* lift_W = (const float*)d_in[1];
    const float* lift_b = (const float*)d_in[2];
    const float* proj_W = (const float*)d_in[3];
    const float* proj_b = (const float*)d_in[4];
    const float* sp_emb = (const float*)d_in[5];
    const float* sp_W   = (const float*)d_in[6];
    const float* sp_b   = (const float*)d_in[7];
    const float* fr_emb = (const float*)d_in[8];
    const float* fr_W   = (const float*)d_in[9];
    const float* fr_b   = (const float*)d_in[10];
    const float* g_W1   = (const float*)d_in[11];
    const float* g_b1   = (const float*)d_in[12];
    const float* g_W2   = (const float*)d_in[13];
    const float* g_b2   = (const float*)d_in[14];
    const float* mhf_Wr = (const float*)d_in[15];
    const float* mhf_Wi = (const float*)d_in[16];
    float* out = (float*)d_out;

    k_twiddle<<<NS / 256, 256>>>();
    k_lift<<<dim3(NS / 64, NB), 256>>>(x, lift_W, lift_b);
    for (int l = 0; l < 4; l++) {
        k_scidx<<<dim3(NS / 256, NB), 256>>>(sp_emb, l);
        k_dft<<<dim3(NCH, NB), 256>>>();
        k_small<<<NB, 256>>>(sp_W, sp_b, fr_emb, fr_W, fr_b,
                             g_W1, g_b1, g_W2, g_b2, mhf_Wr, mhf_Wi, l);
        k_synth<<<dim3(NS / 128, NB), 256>>>(sp_emb, sp_W, sp_b, l);
    }
    k_proj<<<dim3(NS / 256, NB), 256>>>(proj_W, proj_b, out);
}

// round 10
// speedup vs baseline: 1.3422x; 1.3422x over previous
#include <cuda_runtime.h>
#include <cuda_bf16.h>
#include <math.h>
#include <stdint.h>

#define NB 16
#define NS 16384
#define NC 64
#define NM 16
#define NPSP 500
#define NPFR 200
#define NED 8
#define NCH 64          // DFT chunks over s (256 s each)

// -------- scratch (static device globals; no runtime allocation) -----------
__device__ float g_h[NB * NS * NC];                 // [b][s][c]  64 MB
__device__ float g_tw[NS * 32];                     // per s: cos[16], sin[16]
__device__ int   g_idx[NB * NS];                    // spatial engram idx
__device__ float g_xpart[NB * NCH * NC * 32];       // DFT partials (8 MB)
__device__ float g_epart[NB * 64 * NED];            // embedding partial sums
__device__ float g_cR[NB * NC * NM];                // combined mode coef (pre-scaled)
__device__ float g_cI[NB * NC * NM];
__device__ float g_w0[NB];                          // gate weight for sp branch

// ---------------------------------------------------------------------------
// fp32 twiddles with exact integer phase reduction
__global__ void k_twiddle() {
    int s = blockIdx.x * 256 + threadIdx.x;
    if (s >= NS) return;
#pragma unroll
    for (int k = 0; k < 16; k++) {
        int r = (k * s) & (NS - 1);
        float a = (float)r * (2.0f * 3.14159265358979323846f / (float)NS);
        float sv, cv; sincosf(a, &sv, &cv);
        g_tw[s * 32 + k]      = cv;
        g_tw[s * 32 + 16 + k] = sv;
    }
}

// lifting: h[b,s,c] = sum_ci x[b,ci,s] * W[ci,c] + bias[c]
__global__ void k_lift(const float* __restrict__ x,
                       const float* __restrict__ W,
                       const float* __restrict__ bias) {
    __shared__ float lw[3 * NC], lb[NC];
    int b = blockIdx.y, t = threadIdx.x;
    if (t < 192) lw[t] = W[t];
    if (t < NC)  lb[t] = bias[t];
    __syncthreads();
    int c = t & 63, sg = t >> 6;
    const float* xb = x + b * 3 * NS;
    for (int i = 0; i < 16; i++) {
        int s = blockIdx.x * 64 + i * 4 + sg;
        float x0 = xb[s], x1 = xb[NS + s], x2 = xb[2 * NS + s];
        g_h[(b * NS + s) * NC + c] = lb[c] + x0 * lw[c] + x1 * lw[64 + c] + x2 * lw[128 + c];
    }
}

// fused: channel sums (with 4-halo in smem) -> window hash -> idx + emb partials
__global__ void k_scidx(const float* __restrict__ sp_emb, int layer) {
    __shared__ float ssc[260];
    __shared__ float wred[8 * NED];
    int b = blockIdx.y, t = threadIdx.x;
    int base = blockIdx.x * 256;
    for (int j = t; j < 260; j += 256) {
        int s = base + j - 2;
        s = s < 0 ? 0 : (s > NS - 1 ? NS - 1 : s);
        const float4* hp = (const float4*)(g_h + (b * NS + s) * NC);
        float acc = 0.0f;
#pragma unroll
        for (int q = 0; q < 16; q++) {
            float4 v = hp[q];
            acc += v.x; acc += v.y; acc += v.z; acc += v.w;
        }
        ssc[j] = acc;
    }
    __syncthreads();
    int s = base + t;
    float w = ((ssc[t] + ssc[t + 1]) + ssc[t + 2]) + ssc[t + 3];
    int iv = (int)(w * 31.0f);
    iv = ((iv % NPSP) + NPSP) % NPSP;
    g_idx[b * NS + s] = iv;
    const float* em = sp_emb + (layer * NPSP + iv) * NED;
    float ev[NED];
#pragma unroll
    for (int e = 0; e < NED; e++) ev[e] = em[e];
#pragma unroll
    for (int off = 16; off > 0; off >>= 1) {
#pragma unroll
        for (int e = 0; e < NED; e++)
            ev[e] += __shfl_xor_sync(0xffffffffu, ev[e], off);
    }
    int wid = t >> 5, lid = t & 31;
    if (lid == 0) {
#pragma unroll
        for (int e = 0; e < NED; e++) wred[wid * NED + e] = ev[e];
    }
    __syncthreads();
    if (t < NED) {
        float acc = 0.f;
#pragma unroll
        for (int ww = 0; ww < 8; ww++) acc += wred[ww * NED + t];
        g_epart[(b * 64 + blockIdx.x) * NED + t] = acc;
    }
}

// 16-mode DFT partials. R6 mapping: c = t&63 (coalesced h), g = t>>6 (warp-uniform tw).
// x4 s-unroll for MLP on the h-load scoreboard chain. 256 s per block (NCH=64).
__global__ void k_dft() {
    __shared__ float red[256 * 32];
    int b = blockIdx.y, chunk = blockIdx.x, t = threadIdx.x;
    int c = t & 63, g = t >> 6;
    float aC[16], aS[16];
#pragma unroll
    for (int k = 0; k < 16; k++) { aC[k] = 0.f; aS[k] = 0.f; }
    const float* hb = g_h + b * NS * NC + c;
    for (int i = 0; i < 64; i += 4) {
        int s0 = chunk * 256 + i * 4 + g;
        // front-batch the 4 h loads (independent -> MLP 4)
        float xv0 = hb[(s0     ) * NC];
        float xv1 = hb[(s0 +  4) * NC];
        float xv2 = hb[(s0 +  8) * NC];
        float xv3 = hb[(s0 + 12) * NC];
        const float4* tw0 = (const float4*)(g_tw + (s0     ) * 32);
        const float4* tw1 = (const float4*)(g_tw + (s0 +  4) * 32);
        const float4* tw2 = (const float4*)(g_tw + (s0 +  8) * 32);
        const float4* tw3 = (const float4*)(g_tw + (s0 + 12) * 32);
#pragma unroll
        for (int q = 0; q < 4; q++) {
            float4 tc = tw0[q], ts = tw0[4 + q];
            aC[4*q+0] += xv0 * tc.x; aC[4*q+1] += xv0 * tc.y;
            aC[4*q+2] += xv0 * tc.z; aC[4*q+3] += xv0 * tc.w;
            aS[4*q+0] += xv0 * ts.x; aS[4*q+1] += xv0 * ts.y;
            aS[4*q+2] += xv0 * ts.z; aS[4*q+3] += xv0 * ts.w;
        }
#pragma unroll
        for (int q = 0; q < 4; q++) {
            float4 tc = tw1[q], ts = tw1[4 + q];
            aC[4*q+0] += xv1 * tc.x; aC[4*q+1] += xv1 * tc.y;
            aC[4*q+2] += xv1 * tc.z; aC[4*q+3] += xv1 * tc.w;
            aS[4*q+0] += xv1 * ts.x; aS[4*q+1] += xv1 * ts.y;
            aS[4*q+2] += xv1 * ts.z; aS[4*q+3] += xv1 * ts.w;
        }
#pragma unroll
        for (int q = 0; q < 4; q++) {
            float4 tc = tw2[q], ts = tw2[4 + q];
            aC[4*q+0] += xv2 * tc.x; aC[4*q+1] += xv2 * tc.y;
            aC[4*q+2] += xv2 * tc.z; aC[4*q+3] += xv2 * tc.w;
            aS[4*q+0] += xv2 * ts.x; aS[4*q+1] += xv2 * ts.y;
            aS[4*q+2] += xv2 * ts.z; aS[4*q+3] += xv2 * ts.w;
        }
#pragma unroll
        for (int q = 0; q < 4; q++) {
            float4 tc = tw3[q], ts = tw3[4 + q];
            aC[4*q+0] += xv3 * tc.x; aC[4*q+1] += xv3 * tc.y;
            aC[4*q+2] += xv3 * tc.z; aC[4*q+3] += xv3 * tc.w;
            aS[4*q+0] += xv3 * ts.x; aS[4*q+1] += xv3 * ts.y;
            aS[4*q+2] += xv3 * ts.z; aS[4*q+3] += xv3 * ts.w;
        }
    }
#pragma unroll
    for (int k = 0; k < 16; k++) { red[t * 32 + k] = aC[k]; red[t * 32 + 16 + k] = aS[k]; }
    __syncthreads();
    if (g == 0) {
        float* dst = g_xpart + ((b * NCH + chunk) * NC + c) * 32;
#pragma unroll
        for (int k = 0; k < 32; k++)
            dst[k] = ((red[c*32+k] + red[(64+c)*32+k]) + red[(128+c)*32+k]) + red[(192+c)*32+k];
    }
}

// per-b small math: X reduce, mags+fr hash, mh einsum, fr proj, gate MLP, coef combine
__global__ void k_small(const float* __restrict__ sp_W, const float* __restrict__ sp_b,
                        const float* __restrict__ fr_emb, const float* __restrict__ fr_W,
                        const float* __restrict__ fr_b,
                        const float* __restrict__ gW1, const float* __restrict__ gb1,
                        const float* __restrict__ gW2, const float* __restrict__ gb2,
                        const float* __restrict__ Wr, const float* __restrict__ Wi,
                        int layer) {
    __shared__ float sXR[1024], sXI[1024], sOR[1024], sOI[1024], sPR[1024];
    __shared__ float sMag[16], sEmb[8], sEm[8], sG[192], sH1[64], sW[3];
    __shared__ int sFidx;
    int b = blockIdx.x, t = threadIdx.x;
    const float invS = 1.0f / (float)NS;

    for (int it = 0; it < 4; it++) {
        int p = t + it * 256;            // p = c*16 + k
        int c = p >> 4, k = p & 15;
        float sc_ = 0.f, ss = 0.f;
        const float* src0 = g_xpart + (b * NCH * NC + c) * 32 + k;
#pragma unroll 8
        for (int ch = 0; ch < NCH; ch++) {
            const float* src = src0 + ch * NC * 32;
            sc_ += src[0]; ss += src[16];
        }
        sXR[p] = sc_; sXI[p] = -ss;      // rfft: Im = -sum x*sin
    }
    __syncthreads();

    if (t < 16) {
        float acc = 0.f;
        for (int c = 0; c < NC; c++) {
            float xr = sXR[c * 16 + t], xi = sXI[c * 16 + t];
            acc += sqrtf(xr * xr + xi * xi);
        }
        sMag[t] = acc * (1.0f / 64.0f);
    }
    __syncthreads();
    if (t == 0) {
        int s = 0;
        for (int m = 0; m < 16; m++) s += (int)(sMag[m] * 1000.0f);
        sFidx = ((s % NPFR) + NPFR) % NPFR;
    }
    __syncthreads();
    if (t < 8) sEmb[t] = fr_emb[(layer * NPFR + sFidx) * NED + t];

    for (int it = 0; it < 4; it++) {
        int p = t + it * 256;
        int oc = p >> 4, m = p & 15;
        int hh = oc >> 4, o = oc & 15;
        float aR = 0.f, aI = 0.f;
#pragma unroll 4
        for (int i = 0; i < 16; i++) {
            float xr = sXR[(hh * 16 + i) * 16 + m];
            float xi = sXI[(hh * 16 + i) * 16 + m];
            int wi_ = (((layer * 4 + hh) * 16 + i) * 16 + o) * 16 + m;
            float wr = Wr[wi_], wim = Wi[wi_];
            aR += xr * wr - xi * wim;
            aI += xr * wim + xi * wr;
        }
        sOR[p] = aR; sOI[p] = aI;
    }
    __syncthreads();

    for (int it = 0; it < 4; it++) {
        int p = t + it * 256;
        int c = p >> 4, m = p & 15;
        float acc = fr_b[layer * 1024 + c * 16 + m];
#pragma unroll
        for (int e = 0; e < NED; e++)
            acc += sEmb[e] * fr_W[(layer * NED + e) * 1024 + c * 16 + m];
        sPR[p] = acc;
    }

    if (t < 8) {
        float acc = 0.f;
#pragma unroll 8
        for (int blk = 0; blk < 64; blk++) acc += g_epart[(b * 64 + blk) * NED + t];
        sEm[t] = acc * invS;
    }
    __syncthreads();

    if (t < 64) {
        float sm = sp_b[layer * NC + t];
#pragma unroll
        for (int e = 0; e < NED; e++) sm += sEm[e] * sp_W[(layer * NED + e) * NC + t];
        sG[t]       = sm;
        sG[64 + t]  = sOR[t * 16] * invS;
        sG[128 + t] = sPR[t * 16] * invS;
    }
    __syncthreads();
    if (t < 64) {
        float acc = gb1[layer * 64 + t];
#pragma unroll 8
        for (int i = 0; i < 192; i++) acc += sG[i] * gW1[(layer * 192 + i) * 64 + t];
        sH1[t] = fmaxf(acc, 0.0f);
    }
    __syncthreads();
    if (t < 3) {
        float acc = gb2[layer * 3 + t];
        for (int i = 0; i < 64; i++) acc += sH1[i] * gW2[(layer * 64 + i) * 3 + t];
        sW[t] = acc;
    }
    __syncthreads();
    if (t == 0) {
        float mx = fmaxf(sW[0], fmaxf(sW[1], sW[2]));
        float e0 = expf(sW[0] - mx), e1 = expf(sW[1] - mx), e2 = expf(sW[2] - mx);
        float inv = 1.0f / (e0 + e1 + e2);
        sW[0] = e0 * inv; sW[1] = e1 * inv; sW[2] = e2 * inv;
        g_w0[b] = sW[0];
    }
    __syncthreads();

    float w1 = sW[1], w2 = sW[2];
    for (int it = 0; it < 4; it++) {
        int p = t + it * 256;
        int k = p & 15;
        float scale = (k == 0) ? invS : 2.0f * invS;
        g_cR[b * 1024 + p] = (w1 * sOR[p] + w2 * sPR[p]) * scale;
        g_cI[b * 1024 + p] = (w1 * sOI[p]) * scale;
    }
}

// fused synthesis: h = gelu( w0*sp + sum_k (cR cos - cI sin) ), in place
__global__ void k_synth(const float* __restrict__ sp_emb,
                        const float* __restrict__ sp_W,
                        const float* __restrict__ sp_b, int layer) {
    __shared__ float sw[NED * NC], sb[NC];
    int b = blockIdx.y, t = threadIdx.x;
    for (int p = t; p < NED * NC; p += 256) sw[p] = sp_W[layer * NED * NC + p];
    if (t < NC) sb[t] = sp_b[layer * NC + t];
    __syncthreads();
    int c = t & 63, sg = t >> 6;
    float cR[16], cI[16];
    const float* crp = g_cR + (b * NC + c) * NM;
    const float* cip = g_cI + (b * NC + c) * NM;
#pragma unroll
    for (int k = 0; k < 16; k++) { cR[k] = crp[k]; cI[k] = cip[k]; }
    float w0 = g_w0[b];
    for (int i = 0; i < 32; i += 2) {
        int s0 = blockIdx.x * 128 + i * 4 + sg;
        int s1 = s0 + 4;
        int iv0 = g_idx[b * NS + s0];
        int iv1 = g_idx[b * NS + s1];
        const float* em0 = sp_emb + (layer * NPSP + iv0) * NED;
        const float* em1 = sp_emb + (layer * NPSP + iv1) * NED;
        float spv0 = sb[c], spv1 = sb[c];
#pragma unroll
        for (int e = 0; e < NED; e++) {
            spv0 += em0[e] * sw[e * NC + c];
            spv1 += em1[e] * sw[e * NC + c];
        }
        const float4* tw0 = (const float4*)(g_tw + s0 * 32);
        const float4* tw1 = (const float4*)(g_tw + s1 * 32);
        float spec0 = 0.f, spec1 = 0.f;
#pragma unroll
        for (int q = 0; q < 4; q++) {
            float4 tc0 = tw0[q];
            spec0 += cR[4*q+0]*tc0.x + cR[4*q+1]*tc0.y + cR[4*q+2]*tc0.z + cR[4*q+3]*tc0.w;
            float4 ts0 = tw0[4 + q];
            spec0 -= cI[4*q+0]*ts0.x + cI[4*q+1]*ts0.y + cI[4*q+2]*ts0.z + cI[4*q+3]*ts0.w;
            float4 tc1 = tw1[q];
            spec1 += cR[4*q+0]*tc1.x + cR[4*q+1]*tc1.y + cR[4*q+2]*tc1.z + cR[4*q+3]*tc1.w;
            float4 ts1 = tw1[4 + q];
            spec1 -= cI[4*q+0]*ts1.x + cI[4*q+1]*ts1.y + cI[4*q+2]*ts1.z + cI[4*q+3]*ts1.w;
        }
        float v0 = w0 * spv0 + spec0;
        float v1 = w0 * spv1 + spec1;
        float gl0 = 0.5f * v0 * (1.0f + erff(v0 * 0.70710678118654752f));
        float gl1 = 0.5f * v1 * (1.0f + erff(v1 * 0.70710678118654752f));
        g_h[(b * NS + s0) * NC + c] = gl0;
        g_h[(b * NS + s1) * NC + c] = gl1;
    }
}

// projection: out[b,0,s] = sum_c h[b,s,c] * Wp[c] + bp
__global__ void k_proj(const float* __restrict__ Wp, const float* __restrict__ bp,
                       float* __restrict__ out) {
    __shared__ float pw[NC];
    int b = blockIdx.y, t = threadIdx.x;
    if (t < NC) pw[t] = Wp[t];
    __syncthreads();
    int s = blockIdx.x * 256 + t;
    const float* hp = g_h + (b * NS + s) * NC;
    float acc = 0.f;
#pragma unroll 16
    for (int c = 0; c < NC; c++) acc += hp[c] * pw[c];
    out[b * NS + s] = acc + bp[0];
}

extern "C" void kernel_launch(void* const* d_in, const int* in_sizes, int n_in,
                              void* d_out, int out_size) {
    const float* x      = (const float*)d_in[0];
    const float* lift_W = (const float*)d_in[1];
    const float* lift_b = (const float*)d_in[2];
    const float* proj_W = (const float*)d_in[3];
    const float* proj_b = (const float*)d_in[4];
    const float* sp_emb = (const float*)d_in[5];
    const float* sp_W   = (const float*)d_in[6];
    const float* sp_b   = (const float*)d_in[7];
    const float* fr_emb = (const float*)d_in[8];
    const float* fr_W   = (const float*)d_in[9];
    const float* fr_b   = (const float*)d_in[10];
    const float* g_W1   = (const float*)d_in[11];
    const float* g_b1   = (const float*)d_in[12];
    const float* g_W2   = (const float*)d_in[13];
    const float* g_b2   = (const float*)d_in[14];
    const float* mhf_Wr = (const float*)d_in[15];
    const float* mhf_Wi = (const float*)d_in[16];
    float* out = (float*)d_out;

    k_twiddle<<<NS / 256, 256>>>();
    k_lift<<<dim3(NS / 64, NB), 256>>>(x, lift_W, lift_b);
    for (int l = 0; l < 4; l++) {
        k_scidx<<<dim3(NS / 256, NB), 256>>>(sp_emb, l);
        k_dft<<<dim3(NCH, NB), 256>>>();
        k_small<<<NB, 256>>>(sp_W, sp_b, fr_emb, fr_W, fr_b,
                             g_W1, g_b1, g_W2, g_b2, mhf_Wr, mhf_Wi, l);
        k_synth<<<dim3(NS / 128, NB), 256>>>(sp_emb, sp_W, sp_b, l);
    }
    k_proj<<<dim3(NS / 256, NB), 256>>>(proj_W, proj_b, out);
}

// round 11
// speedup vs baseline: 1.7033x; 1.2691x over previous
#include <cuda_runtime.h>
#include <cuda_bf16.h>
#include <math.h>
#include <stdint.h>

#define NB 16
#define NS 16384
#define NC 64
#define NM 16
#define NPSP 500
#define NPFR 200
#define NED 8
#define NCH 64          // DFT chunks over s (256 s each)

// -------- scratch (static device globals; no runtime allocation) -----------
__device__ float g_h[NB * NS * NC];                 // [b][s][c]  64 MB
__device__ float g_tw[NS * 32];                     // per s: cos[16], sin[16]
__device__ int   g_idx[NB * NS];                    // spatial engram idx
__device__ float g_xpart[NB * NCH * NC * 32];       // DFT partials (8 MB)
__device__ float g_epart[NB * 64 * NED];            // embedding partial sums
__device__ float g_cR[NB * NC * NM];                // combined mode coef (pre-scaled)
__device__ float g_cI[NB * NC * NM];
__device__ float g_w0[NB];                          // gate weight for sp branch

// ---------------------------------------------------------------------------
// fp32 twiddles with exact integer phase reduction
__global__ void k_twiddle() {
    int s = blockIdx.x * 256 + threadIdx.x;
    if (s >= NS) return;
#pragma unroll
    for (int k = 0; k < 16; k++) {
        int r = (k * s) & (NS - 1);
        float a = (float)r * (2.0f * 3.14159265358979323846f / (float)NS);
        float sv, cv; sincosf(a, &sv, &cv);
        g_tw[s * 32 + k]      = cv;
        g_tw[s * 32 + 16 + k] = sv;
    }
}

// lifting: h[b,s,c] = sum_ci x[b,ci,s] * W[ci,c] + bias[c]
__global__ void k_lift(const float* __restrict__ x,
                       const float* __restrict__ W,
                       const float* __restrict__ bias) {
    __shared__ float lw[3 * NC], lb[NC];
    int b = blockIdx.y, t = threadIdx.x;
    if (t < 192) lw[t] = W[t];
    if (t < NC)  lb[t] = bias[t];
    __syncthreads();
    int c = t & 63, sg = t >> 6;
    const float* xb = x + b * 3 * NS;
    for (int i = 0; i < 16; i++) {
        int s = blockIdx.x * 64 + i * 4 + sg;
        float x0 = xb[s], x1 = xb[NS + s], x2 = xb[2 * NS + s];
        g_h[(b * NS + s) * NC + c] = lb[c] + x0 * lw[c] + x1 * lw[64 + c] + x2 * lw[128 + c];
    }
}

// fused: channel sums (with 4-halo in smem) -> window hash -> idx + emb partials
__global__ void k_scidx(const float* __restrict__ sp_emb, int layer) {
    __shared__ float ssc[260];
    __shared__ float wred[8 * NED];
    int b = blockIdx.y, t = threadIdx.x;
    int base = blockIdx.x * 256;
    for (int j = t; j < 260; j += 256) {
        int s = base + j - 2;
        s = s < 0 ? 0 : (s > NS - 1 ? NS - 1 : s);
        const float4* hp = (const float4*)(g_h + (b * NS + s) * NC);
        float acc = 0.0f;
#pragma unroll
        for (int q = 0; q < 16; q++) {
            float4 v = hp[q];
            acc += v.x; acc += v.y; acc += v.z; acc += v.w;
        }
        ssc[j] = acc;
    }
    __syncthreads();
    int s = base + t;
    float w = ((ssc[t] + ssc[t + 1]) + ssc[t + 2]) + ssc[t + 3];
    int iv = (int)(w * 31.0f);
    iv = ((iv % NPSP) + NPSP) % NPSP;
    g_idx[b * NS + s] = iv;
    const float* em = sp_emb + (layer * NPSP + iv) * NED;
    float ev[NED];
#pragma unroll
    for (int e = 0; e < NED; e++) ev[e] = em[e];
#pragma unroll
    for (int off = 16; off > 0; off >>= 1) {
#pragma unroll
        for (int e = 0; e < NED; e++)
            ev[e] += __shfl_xor_sync(0xffffffffu, ev[e], off);
    }
    int wid = t >> 5, lid = t & 31;
    if (lid == 0) {
#pragma unroll
        for (int e = 0; e < NED; e++) wred[wid * NED + e] = ev[e];
    }
    __syncthreads();
    if (t < NED) {
        float acc = 0.f;
#pragma unroll
        for (int ww = 0; ww < 8; ww++) acc += wred[ww * NED + t];
        g_epart[(b * 64 + blockIdx.x) * NED + t] = acc;
    }
}

// 16-mode DFT partials. tw staged in smem (32KB), buffer reused for reduction.
// c = t&63 (coalesced h), g = t>>6 (warp-uniform tw). 256 s per block.
__global__ void __launch_bounds__(256, 4) k_dft() {
    __shared__ float stw[256 * 32];      // phase A: tw slice; phase B: reduction
    int b = blockIdx.y, chunk = blockIdx.x, t = threadIdx.x;

    // stage tw slice for s in [chunk*256, chunk*256+256): 8192 floats, coalesced
    {
        const float4* gtw = (const float4*)(g_tw + chunk * 256 * 32);
        float4* stw4 = (float4*)stw;
#pragma unroll
        for (int j = 0; j < 8; j++) stw4[t + j * 256] = gtw[t + j * 256];
    }
    __syncthreads();

    int c = t & 63, g = t >> 6;
    float aC[16], aS[16];
#pragma unroll
    for (int k = 0; k < 16; k++) { aC[k] = 0.f; aS[k] = 0.f; }
    const float* hb = g_h + b * NS * NC + c;
    for (int i = 0; i < 64; i += 4) {
        int s0 = chunk * 256 + i * 4 + g;
        int l0 = i * 4 + g;
        // front-batch the 4 h loads (independent -> MLP 4)
        float xv0 = hb[(s0     ) * NC];
        float xv1 = hb[(s0 +  4) * NC];
        float xv2 = hb[(s0 +  8) * NC];
        float xv3 = hb[(s0 + 12) * NC];
        const float4* tw0 = (const float4*)(stw + (l0     ) * 32);
        const float4* tw1 = (const float4*)(stw + (l0 +  4) * 32);
        const float4* tw2 = (const float4*)(stw + (l0 +  8) * 32);
        const float4* tw3 = (const float4*)(stw + (l0 + 12) * 32);
#pragma unroll
        for (int q = 0; q < 4; q++) {
            float4 tc = tw0[q], ts = tw0[4 + q];
            aC[4*q+0] += xv0 * tc.x; aC[4*q+1] += xv0 * tc.y;
            aC[4*q+2] += xv0 * tc.z; aC[4*q+3] += xv0 * tc.w;
            aS[4*q+0] += xv0 * ts.x; aS[4*q+1] += xv0 * ts.y;
            aS[4*q+2] += xv0 * ts.z; aS[4*q+3] += xv0 * ts.w;
        }
#pragma unroll
        for (int q = 0; q < 4; q++) {
            float4 tc = tw1[q], ts = tw1[4 + q];
            aC[4*q+0] += xv1 * tc.x; aC[4*q+1] += xv1 * tc.y;
            aC[4*q+2] += xv1 * tc.z; aC[4*q+3] += xv1 * tc.w;
            aS[4*q+0] += xv1 * ts.x; aS[4*q+1] += xv1 * ts.y;
            aS[4*q+2] += xv1 * ts.z; aS[4*q+3] += xv1 * ts.w;
        }
#pragma unroll
        for (int q = 0; q < 4; q++) {
            float4 tc = tw2[q], ts = tw2[4 + q];
            aC[4*q+0] += xv2 * tc.x; aC[4*q+1] += xv2 * tc.y;
            aC[4*q+2] += xv2 * tc.z; aC[4*q+3] += xv2 * tc.w;
            aS[4*q+0] += xv2 * ts.x; aS[4*q+1] += xv2 * ts.y;
            aS[4*q+2] += xv2 * ts.z; aS[4*q+3] += xv2 * ts.w;
        }
#pragma unroll
        for (int q = 0; q < 4; q++) {
            float4 tc = tw3[q], ts = tw3[4 + q];
            aC[4*q+0] += xv3 * tc.x; aC[4*q+1] += xv3 * tc.y;
            aC[4*q+2] += xv3 * tc.z; aC[4*q+3] += xv3 * tc.w;
            aS[4*q+0] += xv3 * ts.x; aS[4*q+1] += xv3 * ts.y;
            aS[4*q+2] += xv3 * ts.z; aS[4*q+3] += xv3 * ts.w;
        }
    }
    __syncthreads();                     // everyone done reading tw slice
#pragma unroll
    for (int k = 0; k < 16; k++) { stw[t * 32 + k] = aC[k]; stw[t * 32 + 16 + k] = aS[k]; }
    __syncthreads();
    if (g == 0) {
        float* dst = g_xpart + ((b * NCH + chunk) * NC + c) * 32;
#pragma unroll
        for (int k = 0; k < 32; k++)
            dst[k] = ((stw[c*32+k] + stw[(64+c)*32+k]) + stw[(128+c)*32+k]) + stw[(192+c)*32+k];
    }
}

// per-b small math: X reduce, mags+fr hash, mh einsum, fr proj, gate MLP, coef combine
__global__ void k_small(const float* __restrict__ sp_W, const float* __restrict__ sp_b,
                        const float* __restrict__ fr_emb, const float* __restrict__ fr_W,
                        const float* __restrict__ fr_b,
                        const float* __restrict__ gW1, const float* __restrict__ gb1,
                        const float* __restrict__ gW2, const float* __restrict__ gb2,
                        const float* __restrict__ Wr, const float* __restrict__ Wi,
                        int layer) {
    __shared__ float sXR[1024], sXI[1024], sOR[1024], sOI[1024], sPR[1024];
    __shared__ float sMag[16], sEmb[8], sEm[8], sG[192], sH1[64], sW[3];
    __shared__ int sFidx;
    int b = blockIdx.x, t = threadIdx.x;
    const float invS = 1.0f / (float)NS;

    for (int it = 0; it < 4; it++) {
        int p = t + it * 256;            // p = c*16 + k
        int c = p >> 4, k = p & 15;
        float sc_ = 0.f, ss = 0.f;
        const float* src0 = g_xpart + (b * NCH * NC + c) * 32 + k;
#pragma unroll 8
        for (int ch = 0; ch < NCH; ch++) {
            const float* src = src0 + ch * NC * 32;
            sc_ += src[0]; ss += src[16];
        }
        sXR[p] = sc_; sXI[p] = -ss;      // rfft: Im = -sum x*sin
    }
    __syncthreads();

    if (t < 16) {
        float acc = 0.f;
        for (int c = 0; c < NC; c++) {
            float xr = sXR[c * 16 + t], xi = sXI[c * 16 + t];
            acc += sqrtf(xr * xr + xi * xi);
        }
        sMag[t] = acc * (1.0f / 64.0f);
    }
    __syncthreads();
    if (t == 0) {
        int s = 0;
        for (int m = 0; m < 16; m++) s += (int)(sMag[m] * 1000.0f);
        sFidx = ((s % NPFR) + NPFR) % NPFR;
    }
    __syncthreads();
    if (t < 8) sEmb[t] = fr_emb[(layer * NPFR + sFidx) * NED + t];

    for (int it = 0; it < 4; it++) {
        int p = t + it * 256;
        int oc = p >> 4, m = p & 15;
        int hh = oc >> 4, o = oc & 15;
        float aR = 0.f, aI = 0.f;
#pragma unroll 4
        for (int i = 0; i < 16; i++) {
            float xr = sXR[(hh * 16 + i) * 16 + m];
            float xi = sXI[(hh * 16 + i) * 16 + m];
            int wi_ = (((layer * 4 + hh) * 16 + i) * 16 + o) * 16 + m;
            float wr = Wr[wi_], wim = Wi[wi_];
            aR += xr * wr - xi * wim;
            aI += xr * wim + xi * wr;
        }
        sOR[p] = aR; sOI[p] = aI;
    }
    __syncthreads();

    for (int it = 0; it < 4; it++) {
        int p = t + it * 256;
        int c = p >> 4, m = p & 15;
        float acc = fr_b[layer * 1024 + c * 16 + m];
#pragma unroll
        for (int e = 0; e < NED; e++)
            acc += sEmb[e] * fr_W[(layer * NED + e) * 1024 + c * 16 + m];
        sPR[p] = acc;
    }

    if (t < 8) {
        float acc = 0.f;
#pragma unroll 8
        for (int blk = 0; blk < 64; blk++) acc += g_epart[(b * 64 + blk) * NED + t];
        sEm[t] = acc * invS;
    }
    __syncthreads();

    if (t < 64) {
        float sm = sp_b[layer * NC + t];
#pragma unroll
        for (int e = 0; e < NED; e++) sm += sEm[e] * sp_W[(layer * NED + e) * NC + t];
        sG[t]       = sm;
        sG[64 + t]  = sOR[t * 16] * invS;
        sG[128 + t] = sPR[t * 16] * invS;
    }
    __syncthreads();
    if (t < 64) {
        float acc = gb1[layer * 64 + t];
#pragma unroll 8
        for (int i = 0; i < 192; i++) acc += sG[i] * gW1[(layer * 192 + i) * 64 + t];
        sH1[t] = fmaxf(acc, 0.0f);
    }
    __syncthreads();
    if (t < 3) {
        float acc = gb2[layer * 3 + t];
        for (int i = 0; i < 64; i++) acc += sH1[i] * gW2[(layer * 64 + i) * 3 + t];
        sW[t] = acc;
    }
    __syncthreads();
    if (t == 0) {
        float mx = fmaxf(sW[0], fmaxf(sW[1], sW[2]));
        float e0 = expf(sW[0] - mx), e1 = expf(sW[1] - mx), e2 = expf(sW[2] - mx);
        float inv = 1.0f / (e0 + e1 + e2);
        sW[0] = e0 * inv; sW[1] = e1 * inv; sW[2] = e2 * inv;
        g_w0[b] = sW[0];
    }
    __syncthreads();

    float w1 = sW[1], w2 = sW[2];
    for (int it = 0; it < 4; it++) {
        int p = t + it * 256;
        int k = p & 15;
        float scale = (k == 0) ? invS : 2.0f * invS;
        g_cR[b * 1024 + p] = (w1 * sOR[p] + w2 * sPR[p]) * scale;
        g_cI[b * 1024 + p] = (w1 * sOI[p]) * scale;
    }
}

// fused synthesis: h = gelu( w0*sp + sum_k (cR cos - cI sin) ), tw staged in smem
__global__ void k_synth(const float* __restrict__ sp_emb,
                        const float* __restrict__ sp_W,
                        const float* __restrict__ sp_b, int layer) {
    __shared__ float stw[128 * 32];      // tw slice for this block's 128 s (16 KB)
    __shared__ float sw[NED * NC], sb[NC];
    int b = blockIdx.y, t = threadIdx.x;
    {
        const float4* gtw = (const float4*)(g_tw + blockIdx.x * 128 * 32);
        float4* stw4 = (float4*)stw;
#pragma unroll
        for (int j = 0; j < 4; j++) stw4[t + j * 256] = gtw[t + j * 256];
    }
    for (int p = t; p < NED * NC; p += 256) sw[p] = sp_W[layer * NED * NC + p];
    if (t < NC) sb[t] = sp_b[layer * NC + t];
    __syncthreads();
    int c = t & 63, sg = t >> 6;
    float cR[16], cI[16];
    const float* crp = g_cR + (b * NC + c) * NM;
    const float* cip = g_cI + (b * NC + c) * NM;
#pragma unroll
    for (int k = 0; k < 16; k++) { cR[k] = crp[k]; cI[k] = cip[k]; }
    float w0 = g_w0[b];
    for (int i = 0; i < 32; i += 2) {
        int s0 = blockIdx.x * 128 + i * 4 + sg;
        int s1 = s0 + 4;
        int l0 = i * 4 + sg, l1 = l0 + 4;
        int iv0 = g_idx[b * NS + s0];
        int iv1 = g_idx[b * NS + s1];
        const float* em0 = sp_emb + (layer * NPSP + iv0) * NED;
        const float* em1 = sp_emb + (layer * NPSP + iv1) * NED;
        float spv0 = sb[c], spv1 = sb[c];
#pragma unroll
        for (int e = 0; e < NED; e++) {
            spv0 += em0[e] * sw[e * NC + c];
            spv1 += em1[e] * sw[e * NC + c];
        }
        const float4* tw0 = (const float4*)(stw + l0 * 32);
        const float4* tw1 = (const float4*)(stw + l1 * 32);
        float spec0 = 0.f, spec1 = 0.f;
#pragma unroll
        for (int q = 0; q < 4; q++) {
            float4 tc0 = tw0[q];
            spec0 += cR[4*q+0]*tc0.x + cR[4*q+1]*tc0.y + cR[4*q+2]*tc0.z + cR[4*q+3]*tc0.w;
            float4 ts0 = tw0[4 + q];
            spec0 -= cI[4*q+0]*ts0.x + cI[4*q+1]*ts0.y + cI[4*q+2]*ts0.z + cI[4*q+3]*ts0.w;
            float4 tc1 = tw1[q];
            spec1 += cR[4*q+0]*tc1.x + cR[4*q+1]*tc1.y + cR[4*q+2]*tc1.z + cR[4*q+3]*tc1.w;
            float4 ts1 = tw1[4 + q];
            spec1 -= cI[4*q+0]*ts1.x + cI[4*q+1]*ts1.y + cI[4*q+2]*ts1.z + cI[4*q+3]*ts1.w;
        }
        float v0 = w0 * spv0 + spec0;
        float v1 = w0 * spv1 + spec1;
        float gl0 = 0.5f * v0 * (1.0f + erff(v0 * 0.70710678118654752f));
        float gl1 = 0.5f * v1 * (1.0f + erff(v1 * 0.70710678118654752f));
        g_h[(b * NS + s0) * NC + c] = gl0;
        g_h[(b * NS + s1) * NC + c] = gl1;
    }
}

// projection: out[b,0,s] = sum_c h[b,s,c] * Wp[c] + bp
__global__ void k_proj(const float* __restrict__ Wp, const float* __restrict__ bp,
                       float* __restrict__ out) {
    __shared__ float pw[NC];
    int b = blockIdx.y, t = threadIdx.x;
    if (t < NC) pw[t] = Wp[t];
    __syncthreads();
    int s = blockIdx.x * 256 + t;
    const float* hp = g_h + (b * NS + s) * NC;
    float acc = 0.f;
#pragma unroll 16
    for (int c = 0; c < NC; c++) acc += hp[c] * pw[c];
    out[b * NS + s] = acc + bp[0];
}

extern "C" void kernel_launch(void* const* d_in, const int* in_sizes, int n_in,
                              void* d_out, int out_size) {
    const float* x      = (const float*)d_in[0];
    const float* lift_W = (const float*)d_in[1];
    const float* lift_b = (const float*)d_in[2];
    const float* proj_W = (const float*)d_in[3];
    const float* proj_b = (const float*)d_in[4];
    const float* sp_emb = (const float*)d_in[5];
    const float* sp_W   = (const float*)d_in[6];
    const float* sp_b   = (const float*)d_in[7];
    const float* fr_emb = (const float*)d_in[8];
    const float* fr_W   = (const float*)d_in[9];
    const float* fr_b   = (const float*)d_in[10];
    const float* g_W1   = (const float*)d_in[11];
    const float* g_b1   = (const float*)d_in[12];
    const float* g_W2   = (const float*)d_in[13];
    const float* g_b2   = (const float*)d_in[14];
    const float* mhf_Wr = (const float*)d_in[15];
    const float* mhf_Wi = (const float*)d_in[16];
    float* out = (float*)d_out;

    k_twiddle<<<NS / 256, 256>>>();
    k_lift<<<dim3(NS / 64, NB), 256>>>(x, lift_W, lift_b);
    for (int l = 0; l < 4; l++) {
        k_scidx<<<dim3(NS / 256, NB), 256>>>(sp_emb, l);
        k_dft<<<dim3(NCH, NB), 256>>>();
        k_small<<<NB, 256>>>(sp_W, sp_b, fr_emb, fr_W, fr_b,
                             g_W1, g_b1, g_W2, g_b2, mhf_Wr, mhf_Wi, l);
        k_synth<<<dim3(NS / 128, NB), 256>>>(sp_emb, sp_W, sp_b, l);
    }
    k_proj<<<dim3(NS / 256, NB), 256>>>(proj_W, proj_b, out);
}

// round 12
// speedup vs baseline: 1.7644x; 1.0359x over previous
#include <cuda_runtime.h>
#include <cuda_bf16.h>
#include <math.h>
#include <stdint.h>

#define NB 16
#define NS 16384
#define NC 64
#define NM 16
#define NPSP 500
#define NPFR 200
#define NED 8
#define NCH 64          // DFT chunks over s (256 s each)

// -------- scratch (static device globals; no runtime allocation) -----------
__device__ float g_h[NB * NS * NC];                 // [b][s][c]  64 MB
__device__ float g_tw[NS * 32];                     // per s: cos[16], sin[16]
__device__ int   g_idx[NB * NS];                    // spatial engram idx
__device__ float g_xpart[NB * NCH * NC * 32];       // DFT partials (8 MB)
__device__ float g_epart[NB * 64 * NED];            // embedding partial sums
__device__ float g_cR[NB * NC * NM];                // combined mode coef (pre-scaled)
__device__ float g_cI[NB * NC * NM];
__device__ float g_w0[NB];                          // gate weight for sp branch

// ---------------------------------------------------------------------------
// fp32 twiddles with exact integer phase reduction
__global__ void k_twiddle() {
    int s = blockIdx.x * 256 + threadIdx.x;
    if (s >= NS) return;
#pragma unroll
    for (int k = 0; k < 16; k++) {
        int r = (k * s) & (NS - 1);
        float a = (float)r * (2.0f * 3.14159265358979323846f / (float)NS);
        float sv, cv; sincosf(a, &sv, &cv);
        g_tw[s * 32 + k]      = cv;
        g_tw[s * 32 + 16 + k] = sv;
    }
}

// lifting: h[b,s,c] = sum_ci x[b,ci,s] * W[ci,c] + bias[c]
__global__ void k_lift(const float* __restrict__ x,
                       const float* __restrict__ W,
                       const float* __restrict__ bias) {
    __shared__ float lw[3 * NC], lb[NC];
    int b = blockIdx.y, t = threadIdx.x;
    if (t < 192) lw[t] = W[t];
    if (t < NC)  lb[t] = bias[t];
    __syncthreads();
    int c = t & 63, sg = t >> 6;
    const float* xb = x + b * 3 * NS;
    for (int i = 0; i < 16; i++) {
        int s = blockIdx.x * 64 + i * 4 + sg;
        float x0 = xb[s], x1 = xb[NS + s], x2 = xb[2 * NS + s];
        g_h[(b * NS + s) * NC + c] = lb[c] + x0 * lw[c] + x1 * lw[64 + c] + x2 * lw[128 + c];
    }
}

// fused: channel sums (with 4-halo in smem) -> window hash -> idx + emb partials
__global__ void k_scidx(const float* __restrict__ sp_emb, int layer) {
    __shared__ float ssc[260];
    __shared__ float wred[8 * NED];
    int b = blockIdx.y, t = threadIdx.x;
    int base = blockIdx.x * 256;
    for (int j = t; j < 260; j += 256) {
        int s = base + j - 2;
        s = s < 0 ? 0 : (s > NS - 1 ? NS - 1 : s);
        const float4* hp = (const float4*)(g_h + (b * NS + s) * NC);
        float acc = 0.0f;
#pragma unroll
        for (int q = 0; q < 16; q++) {
            float4 v = hp[q];
            acc += v.x; acc += v.y; acc += v.z; acc += v.w;
        }
        ssc[j] = acc;
    }
    __syncthreads();
    int s = base + t;
    float w = ((ssc[t] + ssc[t + 1]) + ssc[t + 2]) + ssc[t + 3];
    int iv = (int)(w * 31.0f);
    iv = ((iv % NPSP) + NPSP) % NPSP;
    g_idx[b * NS + s] = iv;
    const float* em = sp_emb + (layer * NPSP + iv) * NED;
    float ev[NED];
#pragma unroll
    for (int e = 0; e < NED; e++) ev[e] = em[e];
#pragma unroll
    for (int off = 16; off > 0; off >>= 1) {
#pragma unroll
        for (int e = 0; e < NED; e++)
            ev[e] += __shfl_xor_sync(0xffffffffu, ev[e], off);
    }
    int wid = t >> 5, lid = t & 31;
    if (lid == 0) {
#pragma unroll
        for (int e = 0; e < NED; e++) wred[wid * NED + e] = ev[e];
    }
    __syncthreads();
    if (t < NED) {
        float acc = 0.f;
#pragma unroll
        for (int ww = 0; ww < 8; ww++) acc += wred[ww * NED + t];
        g_epart[(b * 64 + blockIdx.x) * NED + t] = acc;
    }
}

// 16-mode DFT partials. tw staged in smem; 16-deep front-batched h loads (MLP 16).
// c = t&63 (coalesced h), g = t>>6 (warp-uniform tw). 256 s per block.
__global__ void __launch_bounds__(256, 3) k_dft() {
    __shared__ float stw[256 * 32];      // phase A: tw slice; phase B: reduction
    int b = blockIdx.y, chunk = blockIdx.x, t = threadIdx.x;

    // stage tw slice for s in [chunk*256, chunk*256+256): 8192 floats, coalesced
    {
        const float4* gtw = (const float4*)(g_tw + chunk * 256 * 32);
        float4* stw4 = (float4*)stw;
#pragma unroll
        for (int j = 0; j < 8; j++) stw4[t + j * 256] = gtw[t + j * 256];
    }
    __syncthreads();

    int c = t & 63, g = t >> 6;
    float aC[16], aS[16];
#pragma unroll
    for (int k = 0; k < 16; k++) { aC[k] = 0.f; aS[k] = 0.f; }
    const float* hb = g_h + b * NS * NC + c;
    for (int i = 0; i < 64; i += 16) {
        int s0 = chunk * 256 + i * 4 + g;
        int l0 = i * 4 + g;
        float xv[16];
#pragma unroll
        for (int u = 0; u < 16; u++)
            xv[u] = hb[(s0 + u * 4) * NC];   // 16 independent lines in flight
#pragma unroll
        for (int u = 0; u < 16; u++) {
            const float4* tw = (const float4*)(stw + (l0 + u * 4) * 32);
            float x = xv[u];
#pragma unroll
            for (int q = 0; q < 4; q++) {
                float4 tc = tw[q], ts = tw[4 + q];
                aC[4*q+0] += x * tc.x; aC[4*q+1] += x * tc.y;
                aC[4*q+2] += x * tc.z; aC[4*q+3] += x * tc.w;
                aS[4*q+0] += x * ts.x; aS[4*q+1] += x * ts.y;
                aS[4*q+2] += x * ts.z; aS[4*q+3] += x * ts.w;
            }
        }
    }
    __syncthreads();                     // everyone done reading tw slice
#pragma unroll
    for (int k = 0; k < 16; k++) { stw[t * 32 + k] = aC[k]; stw[t * 32 + 16 + k] = aS[k]; }
    __syncthreads();
    if (g == 0) {
        float* dst = g_xpart + ((b * NCH + chunk) * NC + c) * 32;
#pragma unroll
        for (int k = 0; k < 32; k++)
            dst[k] = ((stw[c*32+k] + stw[(64+c)*32+k]) + stw[(128+c)*32+k]) + stw[(192+c)*32+k];
    }
}

// per-b small math: X reduce, mags+fr hash, mh einsum, fr proj, gate MLP, coef combine
__global__ void k_small(const float* __restrict__ sp_W, const float* __restrict__ sp_b,
                        const float* __restrict__ fr_emb, const float* __restrict__ fr_W,
                        const float* __restrict__ fr_b,
                        const float* __restrict__ gW1, const float* __restrict__ gb1,
                        const float* __restrict__ gW2, const float* __restrict__ gb2,
                        const float* __restrict__ Wr, const float* __restrict__ Wi,
                        int layer) {
    __shared__ float sXR[1024], sXI[1024], sOR[1024], sOI[1024], sPR[1024];
    __shared__ float sMag[16], sEmb[8], sEm[8], sG[192], sH1[64], sW[3];
    __shared__ int sFidx;
    int b = blockIdx.x, t = threadIdx.x;
    const float invS = 1.0f / (float)NS;

    for (int it = 0; it < 4; it++) {
        int p = t + it * 256;            // p = c*16 + k
        int c = p >> 4, k = p & 15;
        float sc_ = 0.f, ss = 0.f;
        const float* src0 = g_xpart + (b * NCH * NC + c) * 32 + k;
#pragma unroll 8
        for (int ch = 0; ch < NCH; ch++) {
            const float* src = src0 + ch * NC * 32;
            sc_ += src[0]; ss += src[16];
        }
        sXR[p] = sc_; sXI[p] = -ss;      // rfft: Im = -sum x*sin
    }
    __syncthreads();

    if (t < 16) {
        float acc = 0.f;
        for (int c = 0; c < NC; c++) {
            float xr = sXR[c * 16 + t], xi = sXI[c * 16 + t];
            acc += sqrtf(xr * xr + xi * xi);
        }
        sMag[t] = acc * (1.0f / 64.0f);
    }
    __syncthreads();
    if (t == 0) {
        int s = 0;
        for (int m = 0; m < 16; m++) s += (int)(sMag[m] * 1000.0f);
        sFidx = ((s % NPFR) + NPFR) % NPFR;
    }
    __syncthreads();
    if (t < 8) sEmb[t] = fr_emb[(layer * NPFR + sFidx) * NED + t];

    for (int it = 0; it < 4; it++) {
        int p = t + it * 256;
        int oc = p >> 4, m = p & 15;
        int hh = oc >> 4, o = oc & 15;
        float aR = 0.f, aI = 0.f;
#pragma unroll 4
        for (int i = 0; i < 16; i++) {
            float xr = sXR[(hh * 16 + i) * 16 + m];
            float xi = sXI[(hh * 16 + i) * 16 + m];
            int wi_ = (((layer * 4 + hh) * 16 + i) * 16 + o) * 16 + m;
            float wr = Wr[wi_], wim = Wi[wi_];
            aR += xr * wr - xi * wim;
            aI += xr * wim + xi * wr;
        }
        sOR[p] = aR; sOI[p] = aI;
    }
    __syncthreads();

    for (int it = 0; it < 4; it++) {
        int p = t + it * 256;
        int c = p >> 4, m = p & 15;
        float acc = fr_b[layer * 1024 + c * 16 + m];
#pragma unroll
        for (int e = 0; e < NED; e++)
            acc += sEmb[e] * fr_W[(layer * NED + e) * 1024 + c * 16 + m];
        sPR[p] = acc;
    }

    if (t < 8) {
        float acc = 0.f;
#pragma unroll 8
        for (int blk = 0; blk < 64; blk++) acc += g_epart[(b * 64 + blk) * NED + t];
        sEm[t] = acc * invS;
    }
    __syncthreads();

    if (t < 64) {
        float sm = sp_b[layer * NC + t];
#pragma unroll
        for (int e = 0; e < NED; e++) sm += sEm[e] * sp_W[(layer * NED + e) * NC + t];
        sG[t]       = sm;
        sG[64 + t]  = sOR[t * 16] * invS;
        sG[128 + t] = sPR[t * 16] * invS;
    }
    __syncthreads();
    if (t < 64) {
        float acc = gb1[layer * 64 + t];
#pragma unroll 8
        for (int i = 0; i < 192; i++) acc += sG[i] * gW1[(layer * 192 + i) * 64 + t];
        sH1[t] = fmaxf(acc, 0.0f);
    }
    __syncthreads();
    if (t < 3) {
        float acc = gb2[layer * 3 + t];
        for (int i = 0; i < 64; i++) acc += sH1[i] * gW2[(layer * 64 + i) * 3 + t];
        sW[t] = acc;
    }
    __syncthreads();
    if (t == 0) {
        float mx = fmaxf(sW[0], fmaxf(sW[1], sW[2]));
        float e0 = expf(sW[0] - mx), e1 = expf(sW[1] - mx), e2 = expf(sW[2] - mx);
        float inv = 1.0f / (e0 + e1 + e2);
        sW[0] = e0 * inv; sW[1] = e1 * inv; sW[2] = e2 * inv;
        g_w0[b] = sW[0];
    }
    __syncthreads();

    float w1 = sW[1], w2 = sW[2];
    for (int it = 0; it < 4; it++) {
        int p = t + it * 256;
        int k = p & 15;
        float scale = (k == 0) ? invS : 2.0f * invS;
        g_cR[b * 1024 + p] = (w1 * sOR[p] + w2 * sPR[p]) * scale;
        g_cI[b * 1024 + p] = (w1 * sOI[p]) * scale;
    }
}

// fused synthesis: h = gelu( w0*sp + sum_k (cR cos - cI sin) ), tw staged in smem.
// 4-deep batching of the idx -> embedding gather chain.
__global__ void __launch_bounds__(256, 2) k_synth(const float* __restrict__ sp_emb,
                        const float* __restrict__ sp_W,
                        const float* __restrict__ sp_b, int layer) {
    __shared__ float stw[128 * 32];      // tw slice for this block's 128 s (16 KB)
    __shared__ float sw[NED * NC], sb[NC];
    int b = blockIdx.y, t = threadIdx.x;
    {
        const float4* gtw = (const float4*)(g_tw + blockIdx.x * 128 * 32);
        float4* stw4 = (float4*)stw;
#pragma unroll
        for (int j = 0; j < 4; j++) stw4[t + j * 256] = gtw[t + j * 256];
    }
    for (int p = t; p < NED * NC; p += 256) sw[p] = sp_W[layer * NED * NC + p];
    if (t < NC) sb[t] = sp_b[layer * NC + t];
    __syncthreads();
    int c = t & 63, sg = t >> 6;
    float cR[16], cI[16];
    const float* crp = g_cR + (b * NC + c) * NM;
    const float* cip = g_cI + (b * NC + c) * NM;
#pragma unroll
    for (int k = 0; k < 16; k++) { cR[k] = crp[k]; cI[k] = cip[k]; }
    float w0 = g_w0[b];
    for (int i = 0; i < 32; i += 4) {
        int l[4], sarr[4], iv[4];
#pragma unroll
        for (int u = 0; u < 4; u++) {
            l[u] = (i + u) * 4 + sg;
            sarr[u] = blockIdx.x * 128 + l[u];
        }
#pragma unroll
        for (int u = 0; u < 4; u++) iv[u] = g_idx[b * NS + sarr[u]];
        float4 ea[4], eb[4];             // 8 embedding rows in flight
#pragma unroll
        for (int u = 0; u < 4; u++) {
            const float4* em = (const float4*)(sp_emb + (layer * NPSP + iv[u]) * NED);
            ea[u] = em[0]; eb[u] = em[1];
        }
#pragma unroll
        for (int u = 0; u < 4; u++) {
            float spv = sb[c];
            spv += ea[u].x * sw[0 * NC + c];
            spv += ea[u].y * sw[1 * NC + c];
            spv += ea[u].z * sw[2 * NC + c];
            spv += ea[u].w * sw[3 * NC + c];
            spv += eb[u].x * sw[4 * NC + c];
            spv += eb[u].y * sw[5 * NC + c];
            spv += eb[u].z * sw[6 * NC + c];
            spv += eb[u].w * sw[7 * NC + c];
            const float4* tw = (const float4*)(stw + l[u] * 32);
            float spec = 0.f;
#pragma unroll
            for (int q = 0; q < 4; q++) {
                float4 tc = tw[q];
                spec += cR[4*q+0]*tc.x + cR[4*q+1]*tc.y + cR[4*q+2]*tc.z + cR[4*q+3]*tc.w;
                float4 ts = tw[4 + q];
                spec -= cI[4*q+0]*ts.x + cI[4*q+1]*ts.y + cI[4*q+2]*ts.z + cI[4*q+3]*ts.w;
            }
            float v = w0 * spv + spec;
            float gl = 0.5f * v * (1.0f + erff(v * 0.70710678118654752f));
            g_h[(b * NS + sarr[u]) * NC + c] = gl;
        }
    }
}

// projection: out[b,0,s] = sum_c h[b,s,c] * Wp[c] + bp
__global__ void k_proj(const float* __restrict__ Wp, const float* __restrict__ bp,
                       float* __restrict__ out) {
    __shared__ float pw[NC];
    int b = blockIdx.y, t = threadIdx.x;
    if (t < NC) pw[t] = Wp[t];
    __syncthreads();
    int s = blockIdx.x * 256 + t;
    const float* hp = g_h + (b * NS + s) * NC;
    float acc = 0.f;
#pragma unroll 16
    for (int c = 0; c < NC; c++) acc += hp[c] * pw[c];
    out[b * NS + s] = acc + bp[0];
}

extern "C" void kernel_launch(void* const* d_in, const int* in_sizes, int n_in,
                              void* d_out, int out_size) {
    const float* x      = (const float*)d_in[0];
    const float* lift_W = (const float*)d_in[1];
    const float* lift_b = (const float*)d_in[2];
    const float* proj_W = (const float*)d_in[3];
    const float* proj_b = (const float*)d_in[4];
    const float* sp_emb = (const float*)d_in[5];
    const float* sp_W   = (const float*)d_in[6];
    const float* sp_b   = (const float*)d_in[7];
    const float* fr_emb = (const float*)d_in[8];
    const float* fr_W   = (const float*)d_in[9];
    const float* fr_b   = (const float*)d_in[10];
    const float* g_W1   = (const float*)d_in[11];
    const float* g_b1   = (const float*)d_in[12];
    const float* g_W2   = (const float*)d_in[13];
    const float* g_b2   = (const float*)d_in[14];
    const float* mhf_Wr = (const float*)d_in[15];
    const float* mhf_Wi = (const float*)d_in[16];
    float* out = (float*)d_out;

    k_twiddle<<<NS / 256, 256>>>();
    k_lift<<<dim3(NS / 64, NB), 256>>>(x, lift_W, lift_b);
    for (int l = 0; l < 4; l++) {
        k_scidx<<<dim3(NS / 256, NB), 256>>>(sp_emb, l);
        k_dft<<<dim3(NCH, NB), 256>>>();
        k_small<<<NB, 256>>>(sp_W, sp_b, fr_emb, fr_W, fr_b,
                             g_W1, g_b1, g_W2, g_b2, mhf_Wr, mhf_Wi, l);
        k_synth<<<dim3(NS / 128, NB), 256>>>(sp_emb, sp_W, sp_b, l);
    }
    k_proj<<<dim3(NS / 256, NB), 256>>>(proj_W, proj_b, out);
}

// round 13
// speedup vs baseline: 2.0429x; 1.1578x over previous
#include <cuda_runtime.h>
#include <cuda_bf16.h>
#include <math.h>
#include <stdint.h>

#define NB 16
#define NS 16384
#define NC 64
#define NM 16
#define NPSP 500
#define NPFR 200
#define NED 8
#define NCH 64          // DFT chunks over s (256 s each)

typedef unsigned long long ull;

__device__ __forceinline__ ull f2pack(float lo, float hi) {
    ull r; asm("mov.b64 %0, {%1,%2};" : "=l"(r) : "f"(lo), "f"(hi)); return r;
}
__device__ __forceinline__ void f2unpack(ull v, float& lo, float& hi) {
    asm("mov.b64 {%0,%1}, %2;" : "=f"(lo), "=f"(hi) : "l"(v));
}
__device__ __forceinline__ ull f2fma(ull a, ull b, ull c) {
    ull d; asm("fma.rn.f32x2 %0, %1, %2, %3;" : "=l"(d) : "l"(a), "l"(b), "l"(c)); return d;
}

// -------- scratch (static device globals; no runtime allocation) -----------
__device__ float g_h[NB * NS * NC];                 // [b][s][c]  64 MB
__device__ float g_tw[NS * 32];                     // per s: cos[16], sin[16]
__device__ int   g_idx[NB * NS];                    // spatial engram idx
__device__ float g_xpart[NB * NCH * NC * 32];       // DFT partials (8 MB)
__device__ float g_epart[NB * 64 * NED];            // embedding partial sums
__device__ float g_cR[NB * NC * NM];                // combined mode coef (pre-scaled)
__device__ float g_cI[NB * NC * NM];
__device__ float g_w0[NB];                          // gate weight for sp branch

// ---------------------------------------------------------------------------
// fp32 twiddles with exact integer phase reduction
__global__ void k_twiddle() {
    int s = blockIdx.x * 256 + threadIdx.x;
    if (s >= NS) return;
#pragma unroll
    for (int k = 0; k < 16; k++) {
        int r = (k * s) & (NS - 1);
        float a = (float)r * (2.0f * 3.14159265358979323846f / (float)NS);
        float sv, cv; sincosf(a, &sv, &cv);
        g_tw[s * 32 + k]      = cv;
        g_tw[s * 32 + 16 + k] = sv;
    }
}

// lifting: h[b,s,c] = sum_ci x[b,ci,s] * W[ci,c] + bias[c]
__global__ void k_lift(const float* __restrict__ x,
                       const float* __restrict__ W,
                       const float* __restrict__ bias) {
    __shared__ float lw[3 * NC], lb[NC];
    int b = blockIdx.y, t = threadIdx.x;
    if (t < 192) lw[t] = W[t];
    if (t < NC)  lb[t] = bias[t];
    __syncthreads();
    int c = t & 63, sg = t >> 6;
    const float* xb = x + b * 3 * NS;
    for (int i = 0; i < 16; i++) {
        int s = blockIdx.x * 64 + i * 4 + sg;
        float x0 = xb[s], x1 = xb[NS + s], x2 = xb[2 * NS + s];
        g_h[(b * NS + s) * NC + c] = lb[c] + x0 * lw[c] + x1 * lw[64 + c] + x2 * lw[128 + c];
    }
}

// fused: channel sums (with 4-halo in smem) -> window hash -> idx + emb partials
__global__ void k_scidx(const float* __restrict__ sp_emb, int layer) {
    __shared__ float ssc[260];
    __shared__ float wred[8 * NED];
    int b = blockIdx.y, t = threadIdx.x;
    int base = blockIdx.x * 256;
    for (int j = t; j < 260; j += 256) {
        int s = base + j - 2;
        s = s < 0 ? 0 : (s > NS - 1 ? NS - 1 : s);
        const float4* hp = (const float4*)(g_h + (b * NS + s) * NC);
        float acc = 0.0f;
#pragma unroll
        for (int q = 0; q < 16; q++) {
            float4 v = hp[q];
            acc += v.x; acc += v.y; acc += v.z; acc += v.w;
        }
        ssc[j] = acc;
    }
    __syncthreads();
    int s = base + t;
    float w = ((ssc[t] + ssc[t + 1]) + ssc[t + 2]) + ssc[t + 3];
    int iv = (int)(w * 31.0f);
    iv = ((iv % NPSP) + NPSP) % NPSP;
    g_idx[b * NS + s] = iv;
    const float* em = sp_emb + (layer * NPSP + iv) * NED;
    float ev[NED];
#pragma unroll
    for (int e = 0; e < NED; e++) ev[e] = em[e];
#pragma unroll
    for (int off = 16; off > 0; off >>= 1) {
#pragma unroll
        for (int e = 0; e < NED; e++)
            ev[e] += __shfl_xor_sync(0xffffffffu, ev[e], off);
    }
    int wid = t >> 5, lid = t & 31;
    if (lid == 0) {
#pragma unroll
        for (int e = 0; e < NED; e++) wred[wid * NED + e] = ev[e];
    }
    __syncthreads();
    if (t < NED) {
        float acc = 0.f;
#pragma unroll
        for (int ww = 0; ww < 8; ww++) acc += wred[ww * NED + t];
        g_epart[(b * 64 + blockIdx.x) * NED + t] = acc;
    }
}

// 16-mode DFT partials. One warp per s (2 channels/lane), f32x2 FFMA pairs along k.
// Per s per warp: 2 LDG wavefronts + 8 LDS.128 (was 18 wf with 2 warps/s).
__global__ void __launch_bounds__(256, 2) k_dft() {
    __shared__ float stw[256 * 32];      // A: tw slice; B: cos reduce; C: sin reduce
    int b = blockIdx.y, chunk = blockIdx.x, t = threadIdx.x;
    {
        const float4* gtw = (const float4*)(g_tw + chunk * 256 * 32);
        float4* stw4 = (float4*)stw;
#pragma unroll
        for (int j = 0; j < 8; j++) stw4[t + j * 256] = gtw[t + j * 256];
    }
    __syncthreads();

    int wid = t >> 5, lane = t & 31;
    int c0 = lane * 2;
    ull aC0[8], aC1[8], aS0[8], aS1[8];
#pragma unroll
    for (int j = 0; j < 8; j++) { aC0[j] = 0ull; aC1[j] = 0ull; aS0[j] = 0ull; aS1[j] = 0ull; }
    // h as float2 per lane: element index (b*NS+s)*32 + lane
    const float2* hb2 = (const float2*)(g_h + (size_t)b * NS * NC) + (size_t)chunk * 256 * 32 + lane;

    for (int j = 0; j < 32; j += 8) {
        float2 xv[8];
#pragma unroll
        for (int u = 0; u < 8; u++) {
            int sl = (j + u) * 8 + wid;
            xv[u] = hb2[sl * 32];
        }
#pragma unroll
        for (int u = 0; u < 8; u++) {
            int sl = (j + u) * 8 + wid;
            const ulonglong2* tw = (const ulonglong2*)(stw + sl * 32);
            ull d0 = f2pack(xv[u].x, xv[u].x);
            ull d1 = f2pack(xv[u].y, xv[u].y);
#pragma unroll
            for (int q = 0; q < 4; q++) {
                ulonglong2 tc = tw[q];
                aC0[2*q]   = f2fma(d0, tc.x, aC0[2*q]);
                aC0[2*q+1] = f2fma(d0, tc.y, aC0[2*q+1]);
                aC1[2*q]   = f2fma(d1, tc.x, aC1[2*q]);
                aC1[2*q+1] = f2fma(d1, tc.y, aC1[2*q+1]);
            }
#pragma unroll
            for (int q = 0; q < 4; q++) {
                ulonglong2 ts = tw[4 + q];
                aS0[2*q]   = f2fma(d0, ts.x, aS0[2*q]);
                aS0[2*q+1] = f2fma(d0, ts.y, aS0[2*q+1]);
                aS1[2*q]   = f2fma(d1, ts.x, aS1[2*q]);
                aS1[2*q+1] = f2fma(d1, ts.y, aS1[2*q+1]);
            }
        }
    }
    __syncthreads();                     // done reading tw slice

    float* xp = g_xpart + ((size_t)(b * NCH + chunk) * NC) * 32;
    // ---- cos reduce pass: scr[(k*64 + c)*8 + wid]
#pragma unroll
    for (int j = 0; j < 8; j++) {
        float lo, hi;
        f2unpack(aC0[j], lo, hi);
        stw[((2*j)   * 64 + c0) * 8 + wid] = lo;
        stw[((2*j+1) * 64 + c0) * 8 + wid] = hi;
        f2unpack(aC1[j], lo, hi);
        stw[((2*j)   * 64 + c0 + 1) * 8 + wid] = lo;
        stw[((2*j+1) * 64 + c0 + 1) * 8 + wid] = hi;
    }
    __syncthreads();
#pragma unroll
    for (int it = 0; it < 4; it++) {
        int p = t + it * 256;            // p = k*64 + c
        int k = p >> 6, c = p & 63;
        const float* r = stw + p * 8;
        float a = ((((((r[0] + r[1]) + r[2]) + r[3]) + r[4]) + r[5]) + r[6]) + r[7];
        xp[c * 32 + k] = a;
    }
    __syncthreads();
    // ---- sin reduce pass
#pragma unroll
    for (int j = 0; j < 8; j++) {
        float lo, hi;
        f2unpack(aS0[j], lo, hi);
        stw[((2*j)   * 64 + c0) * 8 + wid] = lo;
        stw[((2*j+1) * 64 + c0) * 8 + wid] = hi;
        f2unpack(aS1[j], lo, hi);
        stw[((2*j)   * 64 + c0 + 1) * 8 + wid] = lo;
        stw[((2*j+1) * 64 + c0 + 1) * 8 + wid] = hi;
    }
    __syncthreads();
#pragma unroll
    for (int it = 0; it < 4; it++) {
        int p = t + it * 256;
        int k = p >> 6, c = p & 63;
        const float* r = stw + p * 8;
        float a = ((((((r[0] + r[1]) + r[2]) + r[3]) + r[4]) + r[5]) + r[6]) + r[7];
        xp[c * 32 + 16 + k] = a;
    }
}

// per-b small math: X reduce, mags+fr hash, mh einsum, fr proj, gate MLP, coef combine
__global__ void k_small(const float* __restrict__ sp_W, const float* __restrict__ sp_b,
                        const float* __restrict__ fr_emb, const float* __restrict__ fr_W,
                        const float* __restrict__ fr_b,
                        const float* __restrict__ gW1, const float* __restrict__ gb1,
                        const float* __restrict__ gW2, const float* __restrict__ gb2,
                        const float* __restrict__ Wr, const float* __restrict__ Wi,
                        int layer) {
    __shared__ float sXR[1024], sXI[1024], sOR[1024], sOI[1024], sPR[1024];
    __shared__ float sMag[16], sEmb[8], sEm[8], sG[192], sH1[64], sW[3];
    __shared__ int sFidx;
    int b = blockIdx.x, t = threadIdx.x;
    const float invS = 1.0f / (float)NS;

    for (int it = 0; it < 4; it++) {
        int p = t + it * 256;            // p = c*16 + k
        int c = p >> 4, k = p & 15;
        float sc_ = 0.f, ss = 0.f;
        const float* src0 = g_xpart + (b * NCH * NC + c) * 32 + k;
#pragma unroll 8
        for (int ch = 0; ch < NCH; ch++) {
            const float* src = src0 + ch * NC * 32;
            sc_ += src[0]; ss += src[16];
        }
        sXR[p] = sc_; sXI[p] = -ss;      // rfft: Im = -sum x*sin
    }
    __syncthreads();

    if (t < 16) {
        float acc = 0.f;
        for (int c = 0; c < NC; c++) {
            float xr = sXR[c * 16 + t], xi = sXI[c * 16 + t];
            acc += sqrtf(xr * xr + xi * xi);
        }
        sMag[t] = acc * (1.0f / 64.0f);
    }
    __syncthreads();
    if (t == 0) {
        int s = 0;
        for (int m = 0; m < 16; m++) s += (int)(sMag[m] * 1000.0f);
        sFidx = ((s % NPFR) + NPFR) % NPFR;
    }
    __syncthreads();
    if (t < 8) sEmb[t] = fr_emb[(layer * NPFR + sFidx) * NED + t];

    for (int it = 0; it < 4; it++) {
        int p = t + it * 256;
        int oc = p >> 4, m = p & 15;
        int hh = oc >> 4, o = oc & 15;
        float aR = 0.f, aI = 0.f;
#pragma unroll 4
        for (int i = 0; i < 16; i++) {
            float xr = sXR[(hh * 16 + i) * 16 + m];
            float xi = sXI[(hh * 16 + i) * 16 + m];
            int wi_ = (((layer * 4 + hh) * 16 + i) * 16 + o) * 16 + m;
            float wr = Wr[wi_], wim = Wi[wi_];
            aR += xr * wr - xi * wim;
            aI += xr * wim + xi * wr;
        }
        sOR[p] = aR; sOI[p] = aI;
    }
    __syncthreads();

    for (int it = 0; it < 4; it++) {
        int p = t + it * 256;
        int c = p >> 4, m = p & 15;
        float acc = fr_b[layer * 1024 + c * 16 + m];
#pragma unroll
        for (int e = 0; e < NED; e++)
            acc += sEmb[e] * fr_W[(layer * NED + e) * 1024 + c * 16 + m];
        sPR[p] = acc;
    }

    if (t < 8) {
        float acc = 0.f;
#pragma unroll 8
        for (int blk = 0; blk < 64; blk++) acc += g_epart[(b * 64 + blk) * NED + t];
        sEm[t] = acc * invS;
    }
    __syncthreads();

    if (t < 64) {
        float sm = sp_b[layer * NC + t];
#pragma unroll
        for (int e = 0; e < NED; e++) sm += sEm[e] * sp_W[(layer * NED + e) * NC + t];
        sG[t]       = sm;
        sG[64 + t]  = sOR[t * 16] * invS;
        sG[128 + t] = sPR[t * 16] * invS;
    }
    __syncthreads();
    if (t < 64) {
        float acc = gb1[layer * 64 + t];
#pragma unroll 8
        for (int i = 0; i < 192; i++) acc += sG[i] * gW1[(layer * 192 + i) * 64 + t];
        sH1[t] = fmaxf(acc, 0.0f);
    }
    __syncthreads();
    if (t < 3) {
        float acc = gb2[layer * 3 + t];
        for (int i = 0; i < 64; i++) acc += sH1[i] * gW2[(layer * 64 + i) * 3 + t];
        sW[t] = acc;
    }
    __syncthreads();
    if (t == 0) {
        float mx = fmaxf(sW[0], fmaxf(sW[1], sW[2]));
        float e0 = expf(sW[0] - mx), e1 = expf(sW[1] - mx), e2 = expf(sW[2] - mx);
        float inv = 1.0f / (e0 + e1 + e2);
        sW[0] = e0 * inv; sW[1] = e1 * inv; sW[2] = e2 * inv;
        g_w0[b] = sW[0];
    }
    __syncthreads();

    float w1 = sW[1], w2 = sW[2];
    for (int it = 0; it < 4; it++) {
        int p = t + it * 256;
        int k = p & 15;
        float scale = (k == 0) ? invS : 2.0f * invS;
        g_cR[b * 1024 + p] = (w1 * sOR[p] + w2 * sPR[p]) * scale;
        g_cI[b * 1024 + p] = (w1 * sOI[p]) * scale;
    }
}

// fused synthesis: h = gelu( w0*sp + sum_k (cR cos - cI sin) ), f32x2 spec loop
__global__ void __launch_bounds__(256, 2) k_synth(const float* __restrict__ sp_emb,
                        const float* __restrict__ sp_W,
                        const float* __restrict__ sp_b, int layer) {
    __shared__ float stw[128 * 32];      // tw slice for this block's 128 s (16 KB)
    __shared__ float sw[NED * NC], sb[NC];
    int b = blockIdx.y, t = threadIdx.x;
    {
        const float4* gtw = (const float4*)(g_tw + blockIdx.x * 128 * 32);
        float4* stw4 = (float4*)stw;
#pragma unroll
        for (int j = 0; j < 4; j++) stw4[t + j * 256] = gtw[t + j * 256];
    }
    for (int p = t; p < NED * NC; p += 256) sw[p] = sp_W[layer * NED * NC + p];
    if (t < NC) sb[t] = sp_b[layer * NC + t];
    __syncthreads();
    int c = t & 63, sg = t >> 6;
    ull cRp[8], cIp[8];
    {
        const ull* crp = (const ull*)(g_cR + (b * NC + c) * NM);
        const ull* cip = (const ull*)(g_cI + (b * NC + c) * NM);
#pragma unroll
        for (int j = 0; j < 8; j++) { cRp[j] = crp[j]; cIp[j] = cip[j]; }
    }
    float w0 = g_w0[b];
    for (int i = 0; i < 32; i += 4) {
        int l[4], sarr[4], iv[4];
#pragma unroll
        for (int u = 0; u < 4; u++) {
            l[u] = (i + u) * 4 + sg;
            sarr[u] = blockIdx.x * 128 + l[u];
        }
#pragma unroll
        for (int u = 0; u < 4; u++) iv[u] = g_idx[b * NS + sarr[u]];
        float4 ea[4], eb[4];             // 8 embedding rows in flight
#pragma unroll
        for (int u = 0; u < 4; u++) {
            const float4* em = (const float4*)(sp_emb + (layer * NPSP + iv[u]) * NED);
            ea[u] = em[0]; eb[u] = em[1];
        }
#pragma unroll
        for (int u = 0; u < 4; u++) {
            float spv = sb[c];
            spv += ea[u].x * sw[0 * NC + c];
            spv += ea[u].y * sw[1 * NC + c];
            spv += ea[u].z * sw[2 * NC + c];
            spv += ea[u].w * sw[3 * NC + c];
            spv += eb[u].x * sw[4 * NC + c];
            spv += eb[u].y * sw[5 * NC + c];
            spv += eb[u].z * sw[6 * NC + c];
            spv += eb[u].w * sw[7 * NC + c];
            const ulonglong2* tw2 = (const ulonglong2*)(stw + l[u] * 32);
            ull accC = 0ull, accS = 0ull;
#pragma unroll
            for (int q = 0; q < 4; q++) {
                ulonglong2 tc = tw2[q];
                accC = f2fma(cRp[2*q],   tc.x, accC);
                accC = f2fma(cRp[2*q+1], tc.y, accC);
            }
#pragma unroll
            for (int q = 0; q < 4; q++) {
                ulonglong2 ts = tw2[4 + q];
                accS = f2fma(cIp[2*q],   ts.x, accS);
                accS = f2fma(cIp[2*q+1], ts.y, accS);
            }
            float clo, chi, slo, shi;
            f2unpack(accC, clo, chi);
            f2unpack(accS, slo, shi);
            float spec = (clo + chi) - (slo + shi);
            float v = w0 * spv + spec;
            float gl = 0.5f * v * (1.0f + erff(v * 0.70710678118654752f));
            g_h[(b * NS + sarr[u]) * NC + c] = gl;
        }
    }
}

// projection: out[b,0,s] = sum_c h[b,s,c] * Wp[c] + bp
__global__ void k_proj(const float* __restrict__ Wp, const float* __restrict__ bp,
                       float* __restrict__ out) {
    __shared__ float pw[NC];
    int b = blockIdx.y, t = threadIdx.x;
    if (t < NC) pw[t] = Wp[t];
    __syncthreads();
    int s = blockIdx.x * 256 + t;
    const float* hp = g_h + (b * NS + s) * NC;
    float acc = 0.f;
#pragma unroll 16
    for (int c = 0; c < NC; c++) acc += hp[c] * pw[c];
    out[b * NS + s] = acc + bp[0];
}

extern "C" void kernel_launch(void* const* d_in, const int* in_sizes, int n_in,
                              void* d_out, int out_size) {
    const float* x      = (const float*)d_in[0];
    const float* lift_W = (const float*)d_in[1];
    const float* lift_b = (const float*)d_in[2];
    const float* proj_W = (const float*)d_in[3];
    const float* proj_b = (const float*)d_in[4];
    const float* sp_emb = (const float*)d_in[5];
    const float* sp_W   = (const float*)d_in[6];
    const float* sp_b   = (const float*)d_in[7];
    const float* fr_emb = (const float*)d_in[8];
    const float* fr_W   = (const float*)d_in[9];
    const float* fr_b   = (const float*)d_in[10];
    const float* g_W1   = (const float*)d_in[11];
    const float* g_b1   = (const float*)d_in[12];
    const float* g_W2   = (const float*)d_in[13];
    const float* g_b2   = (const float*)d_in[14];
    const float* mhf_Wr = (const float*)d_in[15];
    const float* mhf_Wi = (const float*)d_in[16];
    float* out = (float*)d_out;

    k_twiddle<<<NS / 256, 256>>>();
    k_lift<<<dim3(NS / 64, NB), 256>>>(x, lift_W, lift_b);
    for (int l = 0; l < 4; l++) {
        k_scidx<<<dim3(NS / 256, NB), 256>>>(sp_emb, l);
        k_dft<<<dim3(NCH, NB), 256>>>();
        k_small<<<NB, 256>>>(sp_W, sp_b, fr_emb, fr_W, fr_b,
                             g_W1, g_b1, g_W2, g_b2, mhf_Wr, mhf_Wi, l);
        k_synth<<<dim3(NS / 128, NB), 256>>>(sp_emb, sp_W, sp_b, l);
    }
    k_proj<<<dim3(NS / 256, NB), 256>>>(proj_W, proj_b, out);
}